// round 3
// baseline (speedup 1.0000x reference)
#include <cuda_runtime.h>
#include <cuda_bf16.h>

// YOLOv1 loss, GB300.
// preds: (BSZ, 7, 7, 90) fp32   gt_boxes: (BSZ, 8, 4) fp32   gt_labels: (BSZ, 8) int32
// out: scalar fp32 total loss.

#define SS      7
#define NB      2
#define NC      80
#define NGT     8
#define FEAT    90            // NB*5 + NC
#define CELLS   49            // SS*SS
#define NPRED   98            // CELLS*NB
#define TPB     128
#define MAX_BSZ 8192

static __device__ double g_partials[MAX_BSZ];

__global__ __launch_bounds__(TPB) void yolo_main(
    const float* __restrict__ preds,
    const float* __restrict__ gt_boxes,
    const int*   __restrict__ gt_labels)
{
    const int bz = blockIdx.x;
    const float* p = preds + (size_t)bz * (CELLS * FEAT);
    const int tid = threadIdx.x;

    // ---- target state (SMEM) ----
    __shared__ float         s_conf[NPRED];
    __shared__ float         s_coord[NPRED][4];
    __shared__ unsigned char s_obj[NPRED];
    __shared__ unsigned char s_cellm[CELLS];
    __shared__ unsigned int  s_cls[CELLS][3];     // 96-bit one-hot mask per cell
    // per-gt scratch
    __shared__ int   s_gi[NGT], s_gj[NGT], s_best[NGT], s_lab[NGT];
    __shared__ float s_iou[NGT], s_cv[NGT][4];
    __shared__ double s_red[TPB];

    // zero target arrays
    for (int i = tid; i < NPRED; i += TPB) {
        s_obj[i] = 0; s_conf[i] = 0.f;
        s_coord[i][0] = 0.f; s_coord[i][1] = 0.f; s_coord[i][2] = 0.f; s_coord[i][3] = 0.f;
    }
    for (int i = tid; i < CELLS; i += TPB) {
        s_cls[i][0] = 0u; s_cls[i][1] = 0u; s_cls[i][2] = 0u;
    }

    // ---- phase 1: per-GT (threads 0..7) ----
    if (tid < NGT) {
        const float* g = gt_boxes + ((size_t)bz * NGT + tid) * 4;
        const float x1 = g[0], y1 = g[1], x2 = g[2], y2 = g[3];
        const float cx = (x1 + x2) * 0.5f, cy = (y1 + y2) * 0.5f;
        const float w = x2 - x1, h = y2 - y1;
        int gi = (int)(cx * (float)SS); gi = min(max(gi, 0), SS - 1);
        int gj = (int)(cy * (float)SS); gj = min(max(gj, 0), SS - 1);

        const float* pc = p + (gj * SS + gi) * FEAT;
        float ious[2];
        #pragma unroll
        for (int b = 0; b < 2; b++) {
            const float px  = pc[b * 5 + 0], py  = pc[b * 5 + 1];
            const float pwr = pc[b * 5 + 2], phr = pc[b * 5 + 3];
            const float pcx = (px + (float)gi) / (float)SS;
            const float pcy = (py + (float)gj) / (float)SS;
            const float pw = pwr * pwr, ph = phr * phr;
            const float bx1 = pcx - pw * 0.5f, by1 = pcy - ph * 0.5f;
            const float bx2 = pcx + pw * 0.5f, by2 = pcy + ph * 0.5f;
            const float ix1 = fmaxf(bx1, x1), iy1 = fmaxf(by1, y1);
            const float ix2 = fminf(bx2, x2), iy2 = fminf(by2, y2);
            const float inter = fmaxf(ix2 - ix1, 0.f) * fmaxf(iy2 - iy1, 0.f);
            const float a1 = fmaxf(bx2 - bx1, 0.f) * fmaxf(by2 - by1, 0.f);
            const float a2 = fmaxf(x2 - x1, 0.f) * fmaxf(y2 - y1, 0.f);
            ious[b] = inter / (a1 + a2 - inter + 1e-6f);
        }
        const int best = (ious[1] > ious[0]) ? 1 : 0;   // argmax: first wins on tie
        s_gi[tid] = gi; s_gj[tid] = gj; s_best[tid] = best; s_iou[tid] = ious[best];
        s_cv[tid][0] = cx * (float)SS - (float)gi;
        s_cv[tid][1] = cy * (float)SS - (float)gj;
        s_cv[tid][2] = sqrtf(w);
        s_cv[tid][3] = sqrtf(h);
        s_lab[tid] = gt_labels[bz * NGT + tid];
    }
    __syncthreads();

    // ---- phase 2: sequential scan (exact last-write-wins semantics) ----
    if (tid == 0) {
        #pragma unroll
        for (int k = 0; k < NGT; k++) {
            const int cell = s_gj[k] * SS + s_gi[k];
            const int pr = cell * 2 + s_best[k];
            s_obj[pr] = 1;
            s_conf[pr] = s_iou[k];
            s_coord[pr][0] = s_cv[k][0]; s_coord[pr][1] = s_cv[k][1];
            s_coord[pr][2] = s_cv[k][2]; s_coord[pr][3] = s_cv[k][3];
            const int l = s_lab[k];
            s_cls[cell][l >> 5] |= (1u << (l & 31));
        }
    }
    __syncthreads();
    for (int i = tid; i < CELLS; i += TPB)
        s_cellm[i] = (unsigned char)(s_obj[2 * i] | s_obj[2 * i + 1]);
    __syncthreads();

    // ---- phase 3: stream preds (float2; per-batch base is 8B aligned) ----
    const float2* __restrict__ p2 = reinterpret_cast<const float2*>(p);
    float acc = 0.f;
    for (int i = tid; i < (CELLS * FEAT) / 2; i += TPB) {
        const float2 v2 = p2[i];
        const int idx0 = 2 * i;
        #pragma unroll
        for (int lane = 0; lane < 2; lane++) {
            const float v = (lane == 0) ? v2.x : v2.y;
            const int idx = idx0 + lane;
            const int cell = idx / FEAT;
            const int f = idx - cell * FEAT;
            if (f < NB * 5) {
                const int b = f / 5;
                const int r = f - b * 5;
                const int pr = cell * 2 + b;
                if (r == 4) {
                    // obj: (v-conf_t)^2 ; noobj: 0.5*v^2 (conf_t==0 there)
                    const float d = v - s_conf[pr];
                    acc += (s_obj[pr] ? 1.0f : 0.5f) * d * d;
                } else {
                    if (s_obj[pr]) {
                        const float d = v - s_coord[pr][r];
                        acc += 5.0f * d * d;
                    }
                }
            } else {
                const int c = f - NB * 5;
                if (s_cellm[cell]) {
                    const float t = ((s_cls[cell][c >> 5] >> (c & 31)) & 1u) ? 1.0f : 0.0f;
                    const float d = v - t;
                    acc += d * d;
                }
            }
        }
    }

    // ---- block reduce (double), deterministic ----
    s_red[tid] = (double)acc;
    __syncthreads();
    #pragma unroll
    for (int s = TPB / 2; s > 0; s >>= 1) {
        if (tid < s) s_red[tid] += s_red[tid + s];
        __syncthreads();
    }
    if (tid == 0) g_partials[bz] = s_red[0];
}

__global__ __launch_bounds__(1024) void yolo_reduce(float* __restrict__ out, int n)
{
    __shared__ double sm[1024];
    double a = 0.0;
    for (int i = threadIdx.x; i < n; i += 1024) a += g_partials[i];
    sm[threadIdx.x] = a;
    __syncthreads();
    #pragma unroll
    for (int s = 512; s > 0; s >>= 1) {
        if (threadIdx.x < s) sm[threadIdx.x] += sm[threadIdx.x + s];
        __syncthreads();
    }
    if (threadIdx.x == 0) out[0] = (float)sm[0];
}

extern "C" void kernel_launch(void* const* d_in, const int* in_sizes, int n_in,
                              void* d_out, int out_size)
{
    const float* preds     = (const float*)d_in[0];
    const float* gt_boxes  = (const float*)d_in[1];
    const int*   gt_labels = (const int*)d_in[2];
    float* out = (float*)d_out;

    int Bsz = in_sizes[0] / (CELLS * FEAT);
    if (Bsz > MAX_BSZ) Bsz = MAX_BSZ;

    yolo_main<<<Bsz, TPB>>>(preds, gt_boxes, gt_labels);
    yolo_reduce<<<1, 1024>>>(out, Bsz);
}

// round 4
// speedup vs baseline: 2.4662x; 2.4662x over previous
#include <cuda_runtime.h>
#include <cuda_bf16.h>

// YOLOv1 loss, GB300 — sparse formulation.
// preds: (BSZ, 7, 7, 90) fp32   gt_boxes: (BSZ, 8, 4) fp32   gt_labels: (BSZ, 8) int32
// out: scalar fp32 total loss.
//
// Only conf scalars (2/90) contribute unconditionally (0.5*v^2 when no obj).
// Coord terms exist only for <=8 object predictors; class terms only for <=8
// object cells. So we gather ~7KB/batch instead of streaming 17.6KB/batch.

#define SS      7
#define NB      2
#define NC      80
#define NGT     8
#define FEAT    90
#define CELLS   49
#define NPRED   98
#define TPB     128
#define MAX_BSZ 8192

static __device__ double       g_partials[MAX_BSZ];
static __device__ unsigned int g_count = 0;

__global__ __launch_bounds__(TPB) void yolo_fused(
    const float* __restrict__ preds,
    const float* __restrict__ gt_boxes,
    const int*   __restrict__ gt_labels,
    float*       __restrict__ out)
{
    const int bz  = blockIdx.x;
    const int tid = threadIdx.x;
    const float* p = preds + (size_t)bz * (CELLS * FEAT);

    // per-GT scratch
    __shared__ int   s_gi[NGT], s_gj[NGT], s_best[NGT], s_lab[NGT];
    __shared__ float s_iou[NGT], s_cv[NGT][4];
    // compact target lists (last-write-wins semantics built serially)
    __shared__ int          n_pr, n_cell;
    __shared__ int          s_pr[NGT];            // predictor index cell*2+b
    __shared__ float        s_prconf[NGT];
    __shared__ float        s_prcoord[NGT][4];
    __shared__ int          s_cell[NGT];
    __shared__ unsigned int s_cmask[NGT][3];      // 96-bit class one-hot union
    __shared__ float        s_wsum[TPB / 32];
    __shared__ bool         s_last;

    // ---- phase 1: per-GT geometry + IoU (threads 0..7) ----
    if (tid < NGT) {
        const float4 g4 = reinterpret_cast<const float4*>(gt_boxes)[(size_t)bz * NGT + tid];
        const float x1 = g4.x, y1 = g4.y, x2 = g4.z, y2 = g4.w;
        const float cx = (x1 + x2) * 0.5f, cy = (y1 + y2) * 0.5f;
        const float w = x2 - x1, h = y2 - y1;
        int gi = (int)(cx * (float)SS); gi = min(max(gi, 0), SS - 1);
        int gj = (int)(cy * (float)SS); gj = min(max(gj, 0), SS - 1);

        const float* pc = p + (gj * SS + gi) * FEAT;
        float ious[2];
        #pragma unroll
        for (int b = 0; b < 2; b++) {
            const float px  = pc[b * 5 + 0], py  = pc[b * 5 + 1];
            const float pwr = pc[b * 5 + 2], phr = pc[b * 5 + 3];
            const float pcx = (px + (float)gi) / (float)SS;
            const float pcy = (py + (float)gj) / (float)SS;
            const float pw = pwr * pwr, ph = phr * phr;
            const float bx1 = pcx - pw * 0.5f, by1 = pcy - ph * 0.5f;
            const float bx2 = pcx + pw * 0.5f, by2 = pcy + ph * 0.5f;
            const float ix1 = fmaxf(bx1, x1), iy1 = fmaxf(by1, y1);
            const float ix2 = fminf(bx2, x2), iy2 = fminf(by2, y2);
            const float inter = fmaxf(ix2 - ix1, 0.f) * fmaxf(iy2 - iy1, 0.f);
            const float a1 = fmaxf(bx2 - bx1, 0.f) * fmaxf(by2 - by1, 0.f);
            const float a2 = fmaxf(x2 - x1, 0.f) * fmaxf(y2 - y1, 0.f);
            ious[b] = inter / (a1 + a2 - inter + 1e-6f);
        }
        const int best = (ious[1] > ious[0]) ? 1 : 0;   // argmax: first wins on tie
        s_gi[tid] = gi; s_gj[tid] = gj; s_best[tid] = best; s_iou[tid] = ious[best];
        s_cv[tid][0] = cx * (float)SS - (float)gi;
        s_cv[tid][1] = cy * (float)SS - (float)gj;
        s_cv[tid][2] = sqrtf(w);
        s_cv[tid][3] = sqrtf(h);
        s_lab[tid] = gt_labels[bz * NGT + tid];
    }
    __syncthreads();

    // ---- phase 2: serial scan -> compact lists (exact last-write-wins) ----
    if (tid == 0) {
        int np = 0, nc = 0;
        #pragma unroll
        for (int k = 0; k < NGT; k++) {
            const int cell = s_gj[k] * SS + s_gi[k];
            const int pr   = cell * 2 + s_best[k];
            // predictor entry: overwrite conf/coord if exists (obj is sticky)
            int j = -1;
            for (int t = 0; t < np; t++) if (s_pr[t] == pr) j = t;
            if (j < 0) { j = np++; s_pr[j] = pr; }
            s_prconf[j] = s_iou[k];
            s_prcoord[j][0] = s_cv[k][0]; s_prcoord[j][1] = s_cv[k][1];
            s_prcoord[j][2] = s_cv[k][2]; s_prcoord[j][3] = s_cv[k][3];
            // cell entry: union of class one-hots
            int e = -1;
            for (int t = 0; t < nc; t++) if (s_cell[t] == cell) e = t;
            if (e < 0) { e = nc++; s_cell[e] = cell; s_cmask[e][0] = 0u; s_cmask[e][1] = 0u; s_cmask[e][2] = 0u; }
            const int l = s_lab[k];
            s_cmask[e][l >> 5] |= (1u << (l & 31));
        }
        n_pr = np; n_cell = nc;
    }
    __syncthreads();

    float acc = 0.f;

    // ---- phase 3a: confidence over all 98 predictors (+ coords for obj) ----
    if (tid < NPRED) {
        const int pr = tid, cell = pr >> 1, b = pr & 1;
        const float* pb = p + cell * FEAT + b * 5;
        const float v = __ldg(pb + 4);
        int hit = -1;
        const int np = n_pr;
        #pragma unroll
        for (int j = 0; j < NGT; j++)
            if (j < np && s_pr[j] == pr) hit = j;
        if (hit >= 0) {
            const float d = v - s_prconf[hit];
            acc += d * d;
            #pragma unroll
            for (int r = 0; r < 4; r++) {
                const float dr = __ldg(pb + r) - s_prcoord[hit][r];
                acc += 5.0f * dr * dr;
            }
        } else {
            acc += 0.5f * v * v;
        }
    }

    // ---- phase 3b: class terms for object cells only ----
    {
        const int tot = n_cell * NC;
        for (int j = tid; j < tot; j += TPB) {
            const int e = j / NC;
            const int c = j - e * NC;
            const float v = __ldg(p + s_cell[e] * FEAT + NB * 5 + c);
            const float t = ((s_cmask[e][c >> 5] >> (c & 31)) & 1u) ? 1.0f : 0.0f;
            const float d = v - t;
            acc += d * d;
        }
    }

    // ---- block reduce: warp shuffles (fp32), tiny fp64 tail ----
    #pragma unroll
    for (int o = 16; o; o >>= 1) acc += __shfl_xor_sync(0xFFFFFFFFu, acc, o);
    if ((tid & 31) == 0) s_wsum[tid >> 5] = acc;
    __syncthreads();
    if (tid == 0) {
        double s = 0.0;
        #pragma unroll
        for (int w = 0; w < TPB / 32; w++) s += (double)s_wsum[w];
        g_partials[bz] = s;
        __threadfence();
        const unsigned int old = atomicAdd(&g_count, 1u);
        s_last = (old == (unsigned int)(gridDim.x - 1));
    }
    __syncthreads();

    // ---- fused final reduction: elected last block, fixed summation order ----
    if (s_last) {
        __threadfence();                       // acquire all blocks' partials
        const int n = gridDim.x;
        double a = 0.0;
        for (int i = tid; i < n; i += TPB) a += g_partials[i];   // fixed order
        __shared__ double s_d[TPB];
        s_d[tid] = a;
        __syncthreads();
        #pragma unroll
        for (int s = TPB / 2; s; s >>= 1) {
            if (tid < s) s_d[tid] += s_d[tid + s];
            __syncthreads();
        }
        if (tid == 0) {
            out[0] = (float)s_d[0];
            g_count = 0;                       // reset for next graph replay
        }
    }
}

extern "C" void kernel_launch(void* const* d_in, const int* in_sizes, int n_in,
                              void* d_out, int out_size)
{
    const float* preds     = (const float*)d_in[0];
    const float* gt_boxes  = (const float*)d_in[1];
    const int*   gt_labels = (const int*)d_in[2];
    float* out = (float*)d_out;

    int Bsz = in_sizes[0] / (CELLS * FEAT);
    if (Bsz > MAX_BSZ) Bsz = MAX_BSZ;

    yolo_fused<<<Bsz, TPB>>>(preds, gt_boxes, gt_labels, out);
}

// round 5
// speedup vs baseline: 4.1362x; 1.6772x over previous
#include <cuda_runtime.h>
#include <cuda_bf16.h>

// YOLOv1 loss, GB300 — sparse, warp-per-batch formulation.
// preds: (BSZ, 7, 7, 90) fp32   gt_boxes: (BSZ, 8, 4) fp32   gt_labels: (BSZ, 8) int32
// out: scalar fp32 total loss.

#define SS      7
#define NB      2
#define NC      80
#define NGT     8
#define FEAT    90
#define CELLS   49
#define NPRED   98
#define WPB     8              // warps (batch elements) per block
#define TPB     (WPB * 32)
#define MAX_BLK 1024

static __device__ double       g_partials[MAX_BLK];
static __device__ unsigned int g_count = 0;

struct WarpTargets {
    int          gi[NGT], gj[NGT], best[NGT], lab[NGT];
    float        iou[NGT], cv[NGT][4];
    int          pr[NGT];           // predictor index cell*2+b
    float        prconf[NGT];
    float        prcoord[NGT][4];
    int          cell[NGT];
    unsigned int cmask[NGT][3];     // 96-bit class one-hot union
    int          n_pr, n_cell;
};

__global__ __launch_bounds__(TPB) void yolo_fused(
    const float* __restrict__ preds,
    const float* __restrict__ gt_boxes,
    const int*   __restrict__ gt_labels,
    float*       __restrict__ out,
    int Bsz)
{
    const int w    = threadIdx.x >> 5;
    const int lane = threadIdx.x & 31;
    const int bz   = blockIdx.x * WPB + w;

    __shared__ WarpTargets wt[WPB];
    __shared__ double      s_part[WPB];
    __shared__ bool        s_last;

    if (lane == 0) s_part[w] = 0.0;

    float acc = 0.f;

    if (bz < Bsz) {
        const float* p = preds + (size_t)bz * (CELLS * FEAT);
        WarpTargets& T = wt[w];

        // ---- front-loaded conf gathers (addresses independent of GT) ----
        float confv[4];
        #pragma unroll
        for (int k = 0; k < 4; k++) {
            const int pr = k * 32 + lane;
            if (pr < NPRED)
                confv[k] = __ldg(p + (pr >> 1) * FEAT + (pr & 1) * 5 + 4);
        }

        // ---- phase 1: per-GT geometry + IoU (lanes 0..7) ----
        if (lane < NGT) {
            const float4 g4 = reinterpret_cast<const float4*>(gt_boxes)[(size_t)bz * NGT + lane];
            const float x1 = g4.x, y1 = g4.y, x2 = g4.z, y2 = g4.w;
            const float cx = (x1 + x2) * 0.5f, cy = (y1 + y2) * 0.5f;
            const float bw = x2 - x1, bh = y2 - y1;
            int gi = (int)(cx * (float)SS); gi = min(max(gi, 0), SS - 1);
            int gj = (int)(cy * (float)SS); gj = min(max(gj, 0), SS - 1);

            const float* pc = p + (gj * SS + gi) * FEAT;
            // issue all 8 box floats up front (independent)
            float pb[2][4];
            #pragma unroll
            for (int b = 0; b < 2; b++) {
                pb[b][0] = __ldg(pc + b * 5 + 0);
                pb[b][1] = __ldg(pc + b * 5 + 1);
                pb[b][2] = __ldg(pc + b * 5 + 2);
                pb[b][3] = __ldg(pc + b * 5 + 3);
            }
            float ious[2];
            #pragma unroll
            for (int b = 0; b < 2; b++) {
                const float pcx = (pb[b][0] + (float)gi) / (float)SS;
                const float pcy = (pb[b][1] + (float)gj) / (float)SS;
                const float pw = pb[b][2] * pb[b][2], ph = pb[b][3] * pb[b][3];
                const float bx1 = pcx - pw * 0.5f, by1 = pcy - ph * 0.5f;
                const float bx2 = pcx + pw * 0.5f, by2 = pcy + ph * 0.5f;
                const float ix1 = fmaxf(bx1, x1), iy1 = fmaxf(by1, y1);
                const float ix2 = fminf(bx2, x2), iy2 = fminf(by2, y2);
                const float inter = fmaxf(ix2 - ix1, 0.f) * fmaxf(iy2 - iy1, 0.f);
                const float a1 = fmaxf(bx2 - bx1, 0.f) * fmaxf(by2 - by1, 0.f);
                const float a2 = fmaxf(x2 - x1, 0.f) * fmaxf(y2 - y1, 0.f);
                ious[b] = inter / (a1 + a2 - inter + 1e-6f);
            }
            const int best = (ious[1] > ious[0]) ? 1 : 0;   // argmax: first wins on tie
            T.gi[lane] = gi; T.gj[lane] = gj; T.best[lane] = best; T.iou[lane] = ious[best];
            T.cv[lane][0] = cx * (float)SS - (float)gi;
            T.cv[lane][1] = cy * (float)SS - (float)gj;
            T.cv[lane][2] = sqrtf(bw);
            T.cv[lane][3] = sqrtf(bh);
            T.lab[lane] = __ldg(gt_labels + bz * NGT + lane);
        }
        __syncwarp();

        // ---- phase 2: serial scan on lane 0 (exact last-write-wins) ----
        if (lane == 0) {
            int np = 0, nc = 0;
            #pragma unroll
            for (int k = 0; k < NGT; k++) {
                const int cell = T.gj[k] * SS + T.gi[k];
                const int pr   = cell * 2 + T.best[k];
                int j = -1;
                for (int t = 0; t < np; t++) if (T.pr[t] == pr) j = t;
                if (j < 0) { j = np++; T.pr[j] = pr; }
                T.prconf[j] = T.iou[k];
                T.prcoord[j][0] = T.cv[k][0]; T.prcoord[j][1] = T.cv[k][1];
                T.prcoord[j][2] = T.cv[k][2]; T.prcoord[j][3] = T.cv[k][3];
                int e = -1;
                for (int t = 0; t < nc; t++) if (T.cell[t] == cell) e = t;
                if (e < 0) {
                    e = nc++; T.cell[e] = cell;
                    T.cmask[e][0] = 0u; T.cmask[e][1] = 0u; T.cmask[e][2] = 0u;
                }
                const int l = T.lab[k];
                T.cmask[e][l >> 5] |= (1u << (l & 31));
            }
            T.n_pr = np; T.n_cell = nc;
        }
        __syncwarp();

        const int np = T.n_pr;
        const int ncl = T.n_cell;

        // ---- phase 3a: confidence (all 98) + coords for object predictors ----
        #pragma unroll
        for (int k = 0; k < 4; k++) {
            const int pr = k * 32 + lane;
            if (pr < NPRED) {
                int hit = -1;
                #pragma unroll
                for (int j = 0; j < NGT; j++)
                    if (j < np && T.pr[j] == pr) hit = j;
                const float v = confv[k];
                if (hit >= 0) {
                    const float d = v - T.prconf[hit];
                    acc += d * d;
                    const float* pb = p + (pr >> 1) * FEAT + (pr & 1) * 5;
                    #pragma unroll
                    for (int r = 0; r < 4; r++) {
                        const float dr = __ldg(pb + r) - T.prcoord[hit][r];
                        acc += 5.0f * dr * dr;
                    }
                } else {
                    acc += 0.5f * v * v;
                }
            }
        }

        // ---- phase 3b: class terms for object cells (float2 loads) ----
        {
            const int tot = ncl * (NC / 2);          // float2 per cell = 40
            for (int j = lane; j < tot; j += 32) {
                const int e  = j / (NC / 2);
                const int c2 = j - e * (NC / 2);
                const float2 v = __ldg(reinterpret_cast<const float2*>(
                                       p + T.cell[e] * FEAT + NB * 5) + c2);
                const int c0 = 2 * c2;
                const float t0 = ((T.cmask[e][c0 >> 5] >> (c0 & 31)) & 1u) ? 1.0f : 0.0f;
                const float t1 = ((T.cmask[e][(c0 + 1) >> 5] >> ((c0 + 1) & 31)) & 1u) ? 1.0f : 0.0f;
                const float d0 = v.x - t0, d1 = v.y - t1;
                acc += d0 * d0 + d1 * d1;
            }
        }
    }

    // ---- warp reduce, then fixed-order block sum (fp64) ----
    #pragma unroll
    for (int o = 16; o; o >>= 1) acc += __shfl_xor_sync(0xFFFFFFFFu, acc, o);
    if (lane == 0) s_part[w] = (double)acc;
    __syncthreads();
    if (threadIdx.x == 0) {
        double s = 0.0;
        #pragma unroll
        for (int i = 0; i < WPB; i++) s += s_part[i];
        g_partials[blockIdx.x] = s;
        __threadfence();
        const unsigned int old = atomicAdd(&g_count, 1u);
        s_last = (old == (unsigned int)(gridDim.x - 1));
    }
    __syncthreads();

    // ---- fused final reduction: elected last block, fixed order ----
    if (s_last) {
        __threadfence();
        const int n = gridDim.x;
        double a = 0.0;
        for (int i = threadIdx.x; i < n; i += TPB) a += g_partials[i];
        __shared__ double s_d[TPB];
        s_d[threadIdx.x] = a;
        __syncthreads();
        #pragma unroll
        for (int s = TPB / 2; s; s >>= 1) {
            if (threadIdx.x < s) s_d[threadIdx.x] += s_d[threadIdx.x + s];
            __syncthreads();
        }
        if (threadIdx.x == 0) {
            out[0] = (float)s_d[0];
            g_count = 0;                 // reset for next graph replay
        }
    }
}

extern "C" void kernel_launch(void* const* d_in, const int* in_sizes, int n_in,
                              void* d_out, int out_size)
{
    const float* preds     = (const float*)d_in[0];
    const float* gt_boxes  = (const float*)d_in[1];
    const int*   gt_labels = (const int*)d_in[2];
    float* out = (float*)d_out;

    int Bsz = in_sizes[0] / (CELLS * FEAT);
    int grid = (Bsz + WPB - 1) / WPB;
    if (grid > MAX_BLK) grid = MAX_BLK;

    yolo_fused<<<grid, TPB>>>(preds, gt_boxes, gt_labels, out, Bsz);
}

// round 6
// speedup vs baseline: 5.0000x; 1.2088x over previous
#include <cuda_runtime.h>
#include <cuda_bf16.h>

// YOLOv1 loss, GB300 — sparse, half-warp-per-batch, vectorized box-region loads.
// preds: (BSZ, 7, 7, 90) fp32   gt_boxes: (BSZ, 8, 4) fp32   gt_labels: (BSZ, 8) int32
// out: scalar fp32 total loss.

#define SS      7
#define NB      2
#define NC      80
#define NGT     8
#define FEAT    90
#define CELLS   49
#define NPRED   98
#define WPB     8                // warps per block
#define TPB     (WPB * 32)
#define BPW     2                // batch elements per warp (one per half-warp)
#define MAX_BLK 512

static __device__ double       g_partials[MAX_BLK];
static __device__ unsigned int g_count = 0;

struct BT {                       // per-batch targets (one per half-warp)
    float         conf_t[NPRED];  // 0 when no object
    float         coord[NGT][4];
    int           cell[NGT];
    unsigned int  cmask[NGT][3];  // 96-bit class one-hot union
    unsigned char hit[NPRED];     // 0 = no obj, else coord idx+1
    unsigned char cellmap[CELLS]; // 0 = unused, else cell idx+1
    int           n_cell;
    // per-GT scratch
    int   gi[NGT], gj[NGT], best[NGT], lab[NGT];
    float iou[NGT], cv[NGT][4];
};

__global__ __launch_bounds__(TPB) void yolo_fused(
    const float* __restrict__ preds,
    const float* __restrict__ gt_boxes,
    const int*   __restrict__ gt_labels,
    float*       __restrict__ out,
    int Bsz)
{
    const int w    = threadIdx.x >> 5;
    const int lane = threadIdx.x & 31;
    const int half = lane >> 4;          // 0 | 1
    const int lh   = lane & 15;          // lane within half-warp
    const int bz   = (blockIdx.x * WPB + w) * BPW + half;

    __shared__ BT     bt[WPB][BPW];
    __shared__ double s_part[WPB];
    __shared__ bool   s_last;

    float acc = 0.f;

    if (bz < Bsz) {
        const float* p = preds + (size_t)bz * (CELLS * FEAT);
        BT& T = bt[w][half];

        // ---- zero target maps (half-warp) ----
        for (int i = lh; i < NPRED; i += 16) { T.conf_t[i] = 0.f; T.hit[i] = 0; }
        for (int i = lh; i < CELLS; i += 16) T.cellmap[i] = 0;

        // ---- phase 1: per-GT geometry + IoU (lh 0..7) ----
        if (lh < NGT) {
            const float4 g4 = reinterpret_cast<const float4*>(gt_boxes)[(size_t)bz * NGT + lh];
            const float x1 = g4.x, y1 = g4.y, x2 = g4.z, y2 = g4.w;
            const float cx = (x1 + x2) * 0.5f, cy = (y1 + y2) * 0.5f;
            const float bw = x2 - x1, bh = y2 - y1;
            int gi = (int)(cx * (float)SS); gi = min(max(gi, 0), SS - 1);
            int gj = (int)(cy * (float)SS); gj = min(max(gj, 0), SS - 1);

            const float* pc = p + (gj * SS + gi) * FEAT;
            float pb[2][4];
            #pragma unroll
            for (int b = 0; b < 2; b++) {        // 8 independent scalar LDGs
                pb[b][0] = __ldg(pc + b * 5 + 0);
                pb[b][1] = __ldg(pc + b * 5 + 1);
                pb[b][2] = __ldg(pc + b * 5 + 2);
                pb[b][3] = __ldg(pc + b * 5 + 3);
            }
            float ious[2];
            #pragma unroll
            for (int b = 0; b < 2; b++) {
                const float pcx = (pb[b][0] + (float)gi) / (float)SS;
                const float pcy = (pb[b][1] + (float)gj) / (float)SS;
                const float pw = pb[b][2] * pb[b][2], ph = pb[b][3] * pb[b][3];
                const float bx1 = pcx - pw * 0.5f, by1 = pcy - ph * 0.5f;
                const float bx2 = pcx + pw * 0.5f, by2 = pcy + ph * 0.5f;
                const float ix1 = fmaxf(bx1, x1), iy1 = fmaxf(by1, y1);
                const float ix2 = fminf(bx2, x2), iy2 = fminf(by2, y2);
                const float inter = fmaxf(ix2 - ix1, 0.f) * fmaxf(iy2 - iy1, 0.f);
                const float a1 = fmaxf(bx2 - bx1, 0.f) * fmaxf(by2 - by1, 0.f);
                const float a2 = fmaxf(x2 - x1, 0.f) * fmaxf(y2 - y1, 0.f);
                ious[b] = inter / (a1 + a2 - inter + 1e-6f);
            }
            const int best = (ious[1] > ious[0]) ? 1 : 0;   // argmax: first wins on tie
            T.gi[lh] = gi; T.gj[lh] = gj; T.best[lh] = best; T.iou[lh] = ious[best];
            T.cv[lh][0] = cx * (float)SS - (float)gi;
            T.cv[lh][1] = cy * (float)SS - (float)gj;
            T.cv[lh][2] = sqrtf(bw);
            T.cv[lh][3] = sqrtf(bh);
            T.lab[lh] = __ldg(gt_labels + bz * NGT + lh);
        }
    }
    __syncwarp();

    if (bz < Bsz) {
        BT& T = bt[w][half];
        const float* p = preds + (size_t)bz * (CELLS * FEAT);

        // ---- phase 2: serial scan, O(1) dedup (lh==0; SIMT-parallel across halves) ----
        if (lh == 0) {
            int np = 0, nc = 0;
            #pragma unroll
            for (int k = 0; k < NGT; k++) {
                const int cell = T.gj[k] * SS + T.gi[k];
                const int pr   = cell * 2 + T.best[k];
                int j;
                const unsigned char h = T.hit[pr];
                if (h) j = h - 1; else { j = np++; T.hit[pr] = (unsigned char)(j + 1); }
                T.conf_t[pr]  = T.iou[k];                 // last-write-wins
                T.coord[j][0] = T.cv[k][0]; T.coord[j][1] = T.cv[k][1];
                T.coord[j][2] = T.cv[k][2]; T.coord[j][3] = T.cv[k][3];
                int e;
                const unsigned char m = T.cellmap[cell];
                if (m) e = m - 1;
                else {
                    e = nc++; T.cellmap[cell] = (unsigned char)(e + 1); T.cell[e] = cell;
                    T.cmask[e][0] = 0u; T.cmask[e][1] = 0u; T.cmask[e][2] = 0u;
                }
                const int l = T.lab[k];
                T.cmask[e][l >> 5] |= (1u << (l & 31));
            }
            T.n_cell = nc;
        }
        __syncwarp();

        // ---- phase 3a: box regions, 5 independent float2 per cell ----
        for (int c = lh; c < CELLS; c += 16) {
            const float2* pc2 = reinterpret_cast<const float2*>(p + c * FEAT);
            const float2 v0 = __ldg(pc2 + 0);   // x0 y0
            const float2 v1 = __ldg(pc2 + 1);   // w0 h0
            const float2 v2 = __ldg(pc2 + 2);   // conf0 x1
            const float2 v3 = __ldg(pc2 + 3);   // y1 w1
            const float2 v4 = __ldg(pc2 + 4);   // h1 conf1

            const int h0 = T.hit[2 * c], h1 = T.hit[2 * c + 1];
            const float d0 = v2.x - T.conf_t[2 * c];
            const float d1 = v4.y - T.conf_t[2 * c + 1];
            acc += (h0 ? 1.0f : 0.5f) * d0 * d0;
            acc += (h1 ? 1.0f : 0.5f) * d1 * d1;
            if (h0) {
                const float* cr = T.coord[h0 - 1];
                const float e0 = v0.x - cr[0], e1 = v0.y - cr[1];
                const float e2 = v1.x - cr[2], e3 = v1.y - cr[3];
                acc += 5.0f * (e0 * e0 + e1 * e1 + e2 * e2 + e3 * e3);
            }
            if (h1) {
                const float* cr = T.coord[h1 - 1];
                const float e0 = v2.y - cr[0], e1 = v3.x - cr[1];
                const float e2 = v3.y - cr[2], e3 = v4.x - cr[3];
                acc += 5.0f * (e0 * e0 + e1 * e1 + e2 * e2 + e3 * e3);
            }
        }

        // ---- phase 3b: class terms for object cells (float2) ----
        {
            const int tot = T.n_cell * (NC / 2);
            for (int j = lh; j < tot; j += 16) {
                const int e  = j / (NC / 2);
                const int c2 = j - e * (NC / 2);
                const float2 v = __ldg(reinterpret_cast<const float2*>(
                                       p + T.cell[e] * FEAT + NB * 5) + c2);
                const int c0 = 2 * c2;
                const float t0 = ((T.cmask[e][c0 >> 5] >> (c0 & 31)) & 1u) ? 1.0f : 0.0f;
                const float t1 = ((T.cmask[e][(c0 + 1) >> 5] >> ((c0 + 1) & 31)) & 1u) ? 1.0f : 0.0f;
                const float d0 = v.x - t0, d1 = v.y - t1;
                acc += d0 * d0 + d1 * d1;
            }
        }
    }

    // ---- warp reduce (covers both half-warps), fixed-order block sum ----
    #pragma unroll
    for (int o = 16; o; o >>= 1) acc += __shfl_xor_sync(0xFFFFFFFFu, acc, o);
    if (lane == 0) s_part[w] = (double)acc;
    __syncthreads();
    if (threadIdx.x == 0) {
        double s = 0.0;
        #pragma unroll
        for (int i = 0; i < WPB; i++) s += s_part[i];
        g_partials[blockIdx.x] = s;
        __threadfence();
        const unsigned int old = atomicAdd(&g_count, 1u);
        s_last = (old == (unsigned int)(gridDim.x - 1));
    }
    __syncthreads();

    // ---- fused final reduction: elected last block, fixed order ----
    if (s_last) {
        __threadfence();
        const int n = gridDim.x;
        double a = 0.0;
        for (int i = threadIdx.x; i < n; i += TPB) a += g_partials[i];
        __shared__ double s_d[TPB];
        s_d[threadIdx.x] = a;
        __syncthreads();
        #pragma unroll
        for (int s = TPB / 2; s; s >>= 1) {
            if (threadIdx.x < s) s_d[threadIdx.x] += s_d[threadIdx.x + s];
            __syncthreads();
        }
        if (threadIdx.x == 0) {
            out[0] = (float)s_d[0];
            g_count = 0;                 // reset for next graph replay
        }
    }
}

extern "C" void kernel_launch(void* const* d_in, const int* in_sizes, int n_in,
                              void* d_out, int out_size)
{
    const float* preds     = (const float*)d_in[0];
    const float* gt_boxes  = (const float*)d_in[1];
    const int*   gt_labels = (const int*)d_in[2];
    float* out = (float*)d_out;

    int Bsz = in_sizes[0] / (CELLS * FEAT);
    int grid = (Bsz + WPB * BPW - 1) / (WPB * BPW);
    if (grid > MAX_BLK) grid = MAX_BLK;

    yolo_fused<<<grid, TPB>>>(preds, gt_boxes, gt_labels, out, Bsz);
}